// round 16
// baseline (speedup 1.0000x reference)
#include <cuda_runtime.h>
#include <cuda_fp16.h>
#include <math.h>
#include <stdint.h>

// Problem constants
#define BSZ   16
#define LSZ   2048
#define HSZ   768
#define NEN   64
#define SPAN  4
#define NPAIR 2016
#define NROWS (BSZ*NPAIR)          // 32256
#define H2DIM 512
#define H3DIM 256

// ---------------- scratch (device globals; resolved ONLY in device code) -----
__device__ __align__(16) float d_nrm[BSZ*NEN*HSZ];
__device__ __align__(16) float d_cos[BSZ*NEN*NEN];
__device__ double d_sacc[BSZ];
__device__ double d_s2acc[BSZ];
__device__ int   d_pi[NPAIR];
__device__ int   d_pj[NPAIR];
// All GEMM operands plain fp16 (single term).
__device__ __align__(16) __half d_embX[BSZ*NEN*HSZ];          // [1024][768]
__device__ __align__(16) __half d_w1x [1536*HSZ];             // [1536][768]
__device__ __align__(16) __half d_w2x [H2DIM*HSZ];            // [512][768]
__device__ __align__(16) __half d_w3x [H3DIM*H2DIM];          // [256][512]
__device__ __align__(16) float d_G [(size_t)BSZ*NEN*1536];    // [G1|G2]
__device__ __align__(16) __half d_H1x[(size_t)NROWS*HSZ];     // [32256][768]
__device__ __align__(16) __half d_H2x[(size_t)NROWS*H2DIM];   // [32256][512]
__device__ __align__(16) float d_H3[(size_t)NROWS*H3DIM];

__device__ __forceinline__ const __half* selA(int s) {
    return s == 0 ? d_embX : (s == 1 ? d_H1x : d_H2x);
}
__device__ __forceinline__ const __half* selB(int s) {
    return s == 0 ? d_w1x : (s == 1 ? d_w2x : d_w3x);
}
__device__ __forceinline__ __half* selWout(int s) {
    return s == 1 ? d_w2x : d_w3x;
}

// ---------------- helpers ----------------------------------------------------
__device__ __forceinline__ uint32_t smem_u32(const void* p) {
    return (uint32_t)__cvta_generic_to_shared(p);
}
#define CP16(dst, src) asm volatile("cp.async.cg.shared.global [%0], [%1], 16;\n" :: "r"(dst), "l"(src))
#define CP_COMMIT()    asm volatile("cp.async.commit_group;\n" ::: "memory")
#define CP_WAIT1()     asm volatile("cp.async.wait_group 1;\n" ::: "memory")
#define CP_WAIT0()     asm volatile("cp.async.wait_group 0;\n" ::: "memory")

__device__ __forceinline__ uint32_t pack_h2(__half a, __half b) {
    __half2 t = __half2(a, b);          // a = low 16 bits
    uint32_t u; memcpy(&u, &t, 4); return u;
}

// ---------------- K1: span max-pool + normalize + fp16 convert ---------------
__global__ void k_emb(const float* __restrict__ x, const int* __restrict__ starts) {
    int be = blockIdx.x;
    int b  = be / NEN;
    int e  = be - b*NEN;
    int s0 = starts[b*NEN + e];
    const float* xb = x + ((size_t)b*LSZ + s0) * HSZ;
    int t = threadIdx.x;                 // 256
    float v[3];
    float ss = 0.f;
#pragma unroll
    for (int r = 0; r < 3; r++) {
        int c = t + r*256;
        float m = xb[c];
        m = fmaxf(m, xb[HSZ   + c]);
        m = fmaxf(m, xb[2*HSZ + c]);
        m = fmaxf(m, xb[3*HSZ + c]);
        v[r] = m;
        ss += m*m;
    }
    __shared__ float red[256];
    red[t] = ss;
    __syncthreads();
    for (int o = 128; o > 0; o >>= 1) {
        if (t < o) red[t] += red[t + o];
        __syncthreads();
    }
    __shared__ float s_inv;
    if (t == 0) s_inv = 1.0f / fmaxf(sqrtf(red[0]), 1e-8f);
    __syncthreads();
    float iv = s_inv;
    __half* ex = d_embX + (size_t)be*HSZ;
#pragma unroll
    for (int r = 0; r < 3; r++) {
        int c = t + r*256;
        d_nrm[be*HSZ + c] = v[r] * iv;
        ex[c] = __float2half_rn(v[r]);
    }
}

// ---------------- K2: pair tables + zero std accumulators --------------------
__global__ void k_pairs() {
    int i = threadIdx.x;                 // 64 threads
    if (i < BSZ) { d_sacc[i] = 0.0; d_s2acc[i] = 0.0; }
    if (i >= NEN - 1) return;
    int off = i*63 - i*(i-1)/2;
    for (int j = i + 1; j < NEN; j++) { d_pi[off] = i; d_pj[off] = j; off++; }
}

// ---------------- K3: cosine matrix + per-CTA std partial sums ---------------
// Wide grid (64 x 16 CTAs). Each CTA reduces its row's 64 cos values locally
// and issues ONE pair of double atomicAdds -> 2048 atomics over 32 addresses.
__global__ void k_cos() {
    int i = blockIdx.x, b = blockIdx.y;
    __shared__ float ni[HSZ];
    __shared__ double wsum[8], wsum2[8];
    int t = threadIdx.x;
    const float* base = d_nrm + (b*NEN + i)*HSZ;
#pragma unroll
    for (int r = 0; r < 3; r++) ni[t + r*256] = base[t + r*256];
    __syncthreads();
    int warp = t >> 5, lane = t & 31;
    double ls = 0.0, ls2 = 0.0;
    for (int j = warp; j < NEN; j += 8) {
        const float* nj = d_nrm + (b*NEN + j)*HSZ;
        float s = 0.f;
        for (int c = lane; c < HSZ; c += 32) s += ni[c] * nj[c];
#pragma unroll
        for (int o = 16; o; o >>= 1) s += __shfl_xor_sync(0xffffffffu, s, o);
        if (lane == 0) {
            d_cos[(b*NEN + i)*NEN + j] = s;
            ls  += (double)s;
            ls2 += (double)s * (double)s;
        }
    }
    if (lane == 0) { wsum[warp] = ls; wsum2[warp] = ls2; }
    __syncthreads();
    if (t == 0) {
        double S = 0.0, Q = 0.0;
#pragma unroll
        for (int wdx = 0; wdx < 8; wdx++) { S += wsum[wdx]; Q += wsum2[wdx]; }
        atomicAdd(&d_sacc[b], S);
        atomicAdd(&d_s2acc[b], Q);
    }
}

// ---------------- weight transpose + fp16 convert -----------------------------
// W: [K][N] row-major -> Out(sel): [N][K] fp16
__global__ void k_expand_t(const float* __restrict__ W, int selOut, int K, int N) {
    __half* Out = selWout(selOut);
    int idx = blockIdx.x*256 + threadIdx.x;
    if (idx >= K*N) return;
    int n = idx / K, k = idx - n*K;
    Out[(size_t)n*K + k] = __float2half_rn(W[(size_t)k*N + n]);
}
// combined [w1a | w1b] transposed -> d_w1x [1536][768] fp16
__global__ void k_expand_w1_t(const float* __restrict__ w1) {
    int idx = blockIdx.x*256 + threadIdx.x;
    if (idx >= 1536*HSZ) return;
    int n = idx / HSZ, k = idx - n*HSZ;
    float v = (n < HSZ) ? w1[(size_t)(1+k)*HSZ + n]
                        : w1[(size_t)(769+k)*HSZ + (n-HSZ)];
    d_w1x[(size_t)n*HSZ + k] = __float2half_rn(v);
}

// ---------------- fp16 tensor-core GEMM (single term) ------------------------
// D = act(A B^T + bias).  A: [M][K] fp16, B: [N][K] fp16.
// outMode 0: d_G fp32 (no relu/bias). 1: d_H2x plain fp16 (relu+bias).
// 2: d_H3 fp32 (relu+bias).
// BM=BN=128, BK=32, 256 threads, warp tile 64x32, double-buffered cp.async.
#define STG_ELEMS  10240
#define AA_OFF     0
#define BH_OFF     5120
#define SMEM_GEMM  (2*STG_ELEMS*2)            // 40960 bytes

__global__ __launch_bounds__(256, 2)
void gemm_fp16(int selA_i, int selB_i, const float* __restrict__ bias,
               int outMode, int M, int N, int K) {
    extern __shared__ __align__(16) __half sm[];
    const __half* A  = selA(selA_i);
    const __half* Bt = selB(selB_i);
    float* Cf = (outMode == 0) ? d_G : d_H3;
    __half* Cx = (outMode == 1) ? d_H2x : nullptr;
    int relu = (outMode != 0);

    int tid = threadIdx.x;
    int bm = blockIdx.y * 128;
    int bn = blockIdx.x * 128;
    int lane = tid & 31, w = tid >> 5;
    int wm = w & 1, wn = w >> 1;
    const int m_off = wm*64, n_off = wn*32;
    int gid = lane >> 2, tig = lane & 3;

    float acc[4][4][4];
#pragma unroll
    for (int i = 0; i < 4; i++)
#pragma unroll
        for (int j = 0; j < 4; j++)
#pragma unroll
            for (int q = 0; q < 4; q++) acc[i][j][q] = 0.f;

    int nk = K >> 5;

    // prefetch tile 0 into stage 0
#pragma unroll
    for (int rr = 0; rr < 2; rr++) {
        int q = tid + rr*256;
        int row = q >> 2, c8 = (q & 3)*8;
        CP16(smem_u32(&sm[AA_OFF + row*40 + c8]), A  + (size_t)(bm + row)*K + c8);
        CP16(smem_u32(&sm[BH_OFF + row*40 + c8]), Bt + (size_t)(bn + row)*K + c8);
    }
    CP_COMMIT();

    for (int kt = 0; kt < nk; kt++) {
        int cur = kt & 1;
        const __half* st = sm + cur*STG_ELEMS;
        if (kt + 1 < nk) {
            int k0 = (kt + 1) << 5;
            __half* nx = (__half*)sm + (cur ^ 1)*STG_ELEMS;
#pragma unroll
            for (int rr = 0; rr < 2; rr++) {
                int q = tid + rr*256;
                int row = q >> 2, c8 = (q & 3)*8;
                CP16(smem_u32(&nx[AA_OFF + row*40 + c8]), A  + (size_t)(bm + row)*K + k0 + c8);
                CP16(smem_u32(&nx[BH_OFF + row*40 + c8]), Bt + (size_t)(bn + row)*K + k0 + c8);
            }
            CP_COMMIT();
            CP_WAIT1();          // tile kt's group complete; kt+1 in flight
        } else {
            CP_WAIT0();          // tail: drain everything
        }
        __syncthreads();

#pragma unroll
        for (int kk = 0; kk < 2; kk++) {
            int kc = kk*16 + tig*2;
            uint32_t af[4][4];
#pragma unroll
            for (int mi = 0; mi < 4; mi++) {
                const __half* pa = &st[AA_OFF + (m_off + mi*16 + gid)*40 + kc];
                af[mi][0] = *(const uint32_t*)(pa);
                af[mi][1] = *(const uint32_t*)(pa + 8*40);
                af[mi][2] = *(const uint32_t*)(pa + 8);
                af[mi][3] = *(const uint32_t*)(pa + 8*40 + 8);
            }
            uint32_t bh[4][2];
#pragma unroll
            for (int nj = 0; nj < 4; nj++) {
                const __half* pbh = &st[BH_OFF + (n_off + nj*8 + gid)*40 + kc];
                bh[nj][0] = *(const uint32_t*)(pbh);
                bh[nj][1] = *(const uint32_t*)(pbh + 8);
            }
#pragma unroll
            for (int mi = 0; mi < 4; mi++)
#pragma unroll
                for (int nj = 0; nj < 4; nj++)
                    asm volatile(
                        "mma.sync.aligned.m16n8k16.row.col.f32.f16.f16.f32 "
                        "{%0,%1,%2,%3}, {%4,%5,%6,%7}, {%8,%9}, {%0,%1,%2,%3};"
                        : "+f"(acc[mi][nj][0]), "+f"(acc[mi][nj][1]),
                          "+f"(acc[mi][nj][2]), "+f"(acc[mi][nj][3])
                        : "r"(af[mi][0]), "r"(af[mi][1]), "r"(af[mi][2]), "r"(af[mi][3]),
                          "r"(bh[nj][0]), "r"(bh[nj][1]));
        }
        __syncthreads();
    }

    // epilogue
#pragma unroll
    for (int mi = 0; mi < 4; mi++) {
        int r0 = bm + m_off + mi*16 + gid;
#pragma unroll
        for (int nj = 0; nj < 4; nj++) {
            int c = bn + n_off + nj*8 + tig*2;
            float bb0 = bias ? bias[c]   : 0.f;
            float bb1 = bias ? bias[c+1] : 0.f;
#pragma unroll
            for (int half = 0; half < 2; half++) {
                int r = r0 + half*8;
                float v0 = acc[mi][nj][half*2+0] + bb0;
                float v1 = acc[mi][nj][half*2+1] + bb1;
                if (relu) { v0 = fmaxf(v0, 0.f); v1 = fmaxf(v1, 0.f); }
                if (Cx) {
                    uint32_t* po = (uint32_t*)Cx;
                    po[((size_t)r*N + c) >> 1] =
                        pack_h2(__float2half_rn(v0), __float2half_rn(v1));
                } else {
                    float2 v; v.x = v0; v.y = v1;
                    *(float2*)&Cf[(size_t)r*N + c] = v;
                }
            }
        }
    }
}

// ---------------- K5: assemble plain fp16 H1 (std computed inline) -----------
__global__ void k_h1(const float* __restrict__ w1, const float* __restrict__ b1,
                     const float* __restrict__ thr) {
    int r = blockIdx.x;
    int b = r / NPAIR;
    int p = r - b*NPAIR;
    int i = d_pi[p], j = d_pj[p];
    double S = d_sacc[b], Q = d_s2acc[b];
    double var = (Q - S*S/4096.0) / 4095.0;
    if (var < 0.0) var = 0.0;
    float stdv = (float)sqrt(var);
    float sim = (d_cos[(b*NEN + i)*NEN + j] - thr[0]) / (stdv + 1e-5f);
    const float* g1 = d_G + (size_t)(b*NEN + i)*1536;
    const float* g2 = d_G + (size_t)(b*NEN + j)*1536 + HSZ;
    uint32_t* po = (uint32_t*)(d_H1x + (size_t)r*HSZ);
    int pidx = threadIdx.x;              // 384 threads, one col-pair each
    int c = pidx*2;
    float v0 = fmaxf(g1[c]   + g2[c]   + sim*w1[c]   + b1[c],   0.f);
    float v1 = fmaxf(g1[c+1] + g2[c+1] + sim*w1[c+1] + b1[c+1], 0.f);
    po[pidx] = pack_h2(__float2half_rn(v0), __float2half_rn(v1));
}

// ---------------- K6: final tiny layer ---------------------------------------
__global__ void k_out(const float* __restrict__ w4, const float* __restrict__ b4,
                      float* __restrict__ out) {
    __shared__ float wsh[H3DIM*2];
    int t = threadIdx.x;
    wsh[t]       = w4[t];
    wsh[t + 256] = w4[t + 256];
    __syncthreads();
    int warp = t >> 5, lane = t & 31;
    int r = blockIdx.x*8 + warp;
    const float* h = d_H3 + (size_t)r*H3DIM;
    float s0 = 0.f, s1 = 0.f;
    for (int c = lane; c < H3DIM; c += 32) {
        float hv = h[c];
        s0 = fmaf(hv, wsh[c*2+0], s0);
        s1 = fmaf(hv, wsh[c*2+1], s1);
    }
#pragma unroll
    for (int o = 16; o; o >>= 1) {
        s0 += __shfl_xor_sync(0xffffffffu, s0, o);
        s1 += __shfl_xor_sync(0xffffffffu, s1, o);
    }
    if (lane == 0) {
        out[r*2 + 0] = s0 + b4[0];
        out[r*2 + 1] = s1 + b4[1];
    }
}

// ---------------- launch -----------------------------------------------------
extern "C" void kernel_launch(void* const* d_in, const int* in_sizes, int n_in,
                              void* d_out, int out_size) {
    const float* x      = (const float*)d_in[0];
    const float* thr    = (const float*)d_in[1];
    const float* w1     = (const float*)d_in[2];
    const float* b1     = (const float*)d_in[3];
    const float* w2     = (const float*)d_in[4];
    const float* b2     = (const float*)d_in[5];
    const float* w3     = (const float*)d_in[6];
    const float* b3     = (const float*)d_in[7];
    const float* w4     = (const float*)d_in[8];
    const float* b4     = (const float*)d_in[9];
    const int*   starts = (const int*)d_in[10];
    float* out = (float*)d_out;

    cudaFuncSetAttribute(gemm_fp16, cudaFuncAttributeMaxDynamicSharedMemorySize,
                         SMEM_GEMM);

    // preprocessing (wide grids — parallelism preserved)
    k_emb<<<BSZ*NEN, 256>>>(x, starts);
    k_pairs<<<1, 64>>>();                 // also zeroes std accumulators
    dim3 gcos(NEN, BSZ);
    k_cos<<<gcos, 256>>>();               // cos + per-CTA std partials

    // weight transposes (all single-plane fp16)
    k_expand_w1_t<<<(1536*HSZ + 255)/256, 256>>>(w1);
    k_expand_t<<<(HSZ*H2DIM + 255)/256, 256>>>(w2, 1, HSZ, H2DIM);
    k_expand_t<<<(H2DIM*H3DIM + 255)/256, 256>>>(w3, 2, H2DIM, H3DIM);

    // G = emb @ [w1a|w1b]   (1024 x 1536, K=768) -> d_G fp32
    {
        dim3 g(1536/128, (BSZ*NEN)/128);     // (12, 8)
        gemm_fp16<<<g, 256, SMEM_GEMM>>>(0, 0, nullptr, 0, BSZ*NEN, 1536, HSZ);
    }

    // H1 assembly -> plain fp16 (std inline)
    k_h1<<<NROWS, 384>>>(w1, b1, thr);

    // layer 2: H2x = relu(H1 @ w2 + b2) fp16   (32256 x 512, K=768)
    {
        dim3 g(H2DIM/128, NROWS/128);        // (4, 252)
        gemm_fp16<<<g, 256, SMEM_GEMM>>>(1, 1, b2, 1, NROWS, H2DIM, HSZ);
    }
    // layer 3: H3 = relu(H2 @ w3 + b3) fp32   (32256 x 256, K=512)
    {
        dim3 g(H3DIM/128, NROWS/128);        // (2, 252)
        gemm_fp16<<<g, 256, SMEM_GEMM>>>(2, 2, b3, 2, NROWS, H3DIM, H2DIM);
    }
    // layer 4
    k_out<<<NROWS/8, 256>>>(w4, b4, out);
}

// round 17
// speedup vs baseline: 2.4512x; 2.4512x over previous
#include <cuda_runtime.h>
#include <cuda_fp16.h>
#include <math.h>
#include <stdint.h>

// Problem constants
#define BSZ   16
#define LSZ   2048
#define HSZ   768
#define NEN   64
#define SPAN  4
#define NPAIR 2016
#define NROWS (BSZ*NPAIR)          // 32256
#define H2DIM 512
#define H3DIM 256

// ---------------- scratch (device globals; resolved ONLY in device code) -----
__device__ __align__(16) float d_nrm[BSZ*NEN*HSZ];
__device__ __align__(16) float d_cos[BSZ*NEN*NEN];
__device__ float d_std[BSZ];
__device__ int   d_pi[NPAIR];
__device__ int   d_pj[NPAIR];
// All GEMM operands plain fp16 (single term).
__device__ __align__(16) __half d_embX[BSZ*NEN*HSZ];          // [1024][768]
__device__ __align__(16) __half d_w1x [1536*HSZ];             // [1536][768]
__device__ __align__(16) __half d_w2x [H2DIM*HSZ];            // [512][768]
__device__ __align__(16) __half d_w3x [H3DIM*H2DIM];          // [256][512]
__device__ __align__(16) float d_G [(size_t)BSZ*NEN*1536];    // [G1|G2]
__device__ __align__(16) __half d_H1x[(size_t)NROWS*HSZ];     // [32256][768]
__device__ __align__(16) __half d_H2x[(size_t)NROWS*H2DIM];   // [32256][512]
__device__ __align__(16) float d_H3[(size_t)NROWS*H3DIM];

__device__ __forceinline__ const __half* selA(int s) {
    return s == 0 ? d_embX : (s == 1 ? d_H1x : d_H2x);
}
__device__ __forceinline__ const __half* selB(int s) {
    return s == 0 ? d_w1x : (s == 1 ? d_w2x : d_w3x);
}
__device__ __forceinline__ __half* selWout(int s) {
    return s == 1 ? d_w2x : d_w3x;
}

// ---------------- helpers ----------------------------------------------------
__device__ __forceinline__ uint32_t smem_u32(const void* p) {
    return (uint32_t)__cvta_generic_to_shared(p);
}
#define CP16(dst, src) asm volatile("cp.async.cg.shared.global [%0], [%1], 16;\n" :: "r"(dst), "l"(src))
#define CP_COMMIT()    asm volatile("cp.async.commit_group;\n" ::: "memory")
#define CP_WAIT1()     asm volatile("cp.async.wait_group 1;\n" ::: "memory")
#define CP_WAIT0()     asm volatile("cp.async.wait_group 0;\n" ::: "memory")

__device__ __forceinline__ uint32_t pack_h2(__half a, __half b) {
    __half2 t = __half2(a, b);          // a = low 16 bits
    uint32_t u; memcpy(&u, &t, 4); return u;
}

// ---------------- K1: span max-pool + normalize + fp16 convert ---------------
__global__ void k_emb(const float* __restrict__ x, const int* __restrict__ starts) {
    int be = blockIdx.x;
    int b  = be / NEN;
    int e  = be - b*NEN;
    int s0 = starts[b*NEN + e];
    const float* xb = x + ((size_t)b*LSZ + s0) * HSZ;
    int t = threadIdx.x;                 // 256
    float v[3];
    float ss = 0.f;
#pragma unroll
    for (int r = 0; r < 3; r++) {
        int c = t + r*256;
        float m = xb[c];
        m = fmaxf(m, xb[HSZ   + c]);
        m = fmaxf(m, xb[2*HSZ + c]);
        m = fmaxf(m, xb[3*HSZ + c]);
        v[r] = m;
        ss += m*m;
    }
    __shared__ float red[256];
    red[t] = ss;
    __syncthreads();
    for (int o = 128; o > 0; o >>= 1) {
        if (t < o) red[t] += red[t + o];
        __syncthreads();
    }
    __shared__ float s_inv;
    if (t == 0) s_inv = 1.0f / fmaxf(sqrtf(red[0]), 1e-8f);
    __syncthreads();
    float iv = s_inv;
    __half* ex = d_embX + (size_t)be*HSZ;
#pragma unroll
    for (int r = 0; r < 3; r++) {
        int c = t + r*256;
        d_nrm[be*HSZ + c] = v[r] * iv;
        ex[c] = __float2half_rn(v[r]);
    }
}

// ---------------- K2: pair tables --------------------------------------------
__global__ void k_pairs() {
    int i = threadIdx.x;
    if (i >= NEN - 1) return;
    int off = i*63 - i*(i-1)/2;
    for (int j = i + 1; j < NEN; j++) { d_pi[off] = i; d_pj[off] = j; off++; }
}

// ---------------- K3: cosine matrix (wide grid — 1024 CTAs, no fp64) ---------
__global__ void k_cos() {
    int i = blockIdx.x, b = blockIdx.y;
    __shared__ float ni[HSZ];
    int t = threadIdx.x;
    const float* base = d_nrm + (b*NEN + i)*HSZ;
#pragma unroll
    for (int r = 0; r < 3; r++) ni[t + r*256] = base[t + r*256];
    __syncthreads();
    int warp = t >> 5, lane = t & 31;
    for (int j = warp; j < NEN; j += 8) {
        const float* nj = d_nrm + (b*NEN + j)*HSZ;
        float s = 0.f;
        for (int c = lane; c < HSZ; c += 32) s += ni[c] * nj[c];
#pragma unroll
        for (int o = 16; o; o >>= 1) s += __shfl_xor_sync(0xffffffffu, s, o);
        if (lane == 0) d_cos[(b*NEN + i)*NEN + j] = s;
    }
}

// ---------------- K4: unbiased std (16 blocks — fp64 isolated here) ----------
__global__ void k_std() {
    int b = blockIdx.x, t = threadIdx.x;
    double s = 0.0, s2 = 0.0;
    for (int k = t; k < NEN*NEN; k += 256) {
        double v = (double)d_cos[b*NEN*NEN + k];
        s += v; s2 += v*v;
    }
    __shared__ double rs[256], rq[256];
    rs[t] = s; rq[t] = s2;
    __syncthreads();
    for (int o = 128; o > 0; o >>= 1) {
        if (t < o) { rs[t] += rs[t+o]; rq[t] += rq[t+o]; }
        __syncthreads();
    }
    if (t == 0) {
        double n = (double)(NEN*NEN);
        double var = (rq[0] - rs[0]*rs[0]/n) / (n - 1.0);
        if (var < 0.0) var = 0.0;
        d_std[b] = (float)sqrt(var);
    }
}

// ---------------- weight transpose + fp16 convert -----------------------------
// W: [K][N] row-major -> Out(sel): [N][K] fp16
__global__ void k_expand_t(const float* __restrict__ W, int selOut, int K, int N) {
    __half* Out = selWout(selOut);
    int idx = blockIdx.x*256 + threadIdx.x;
    if (idx >= K*N) return;
    int n = idx / K, k = idx - n*K;
    Out[(size_t)n*K + k] = __float2half_rn(W[(size_t)k*N + n]);
}
// combined [w1a | w1b] transposed -> d_w1x [1536][768] fp16
__global__ void k_expand_w1_t(const float* __restrict__ w1) {
    int idx = blockIdx.x*256 + threadIdx.x;
    if (idx >= 1536*HSZ) return;
    int n = idx / HSZ, k = idx - n*HSZ;
    float v = (n < HSZ) ? w1[(size_t)(1+k)*HSZ + n]
                        : w1[(size_t)(769+k)*HSZ + (n-HSZ)];
    d_w1x[(size_t)n*HSZ + k] = __float2half_rn(v);
}

// ---------------- fp16 tensor-core GEMM (single term) ------------------------
// D = act(A B^T + bias).  A: [M][K] fp16, B: [N][K] fp16.
// outMode 0: d_G fp32 (no relu/bias). 1: d_H2x plain fp16 (relu+bias).
// 2: d_H3 fp32 (relu+bias).
// BM=BN=128, BK=32, 256 threads, warp tile 64x32, double-buffered cp.async.
#define STG_ELEMS  10240
#define AA_OFF     0
#define BH_OFF     5120
#define SMEM_GEMM  (2*STG_ELEMS*2)            // 40960 bytes

__global__ __launch_bounds__(256, 2)
void gemm_fp16(int selA_i, int selB_i, const float* __restrict__ bias,
               int outMode, int M, int N, int K) {
    extern __shared__ __align__(16) __half sm[];
    const __half* A  = selA(selA_i);
    const __half* Bt = selB(selB_i);
    float* Cf = (outMode == 0) ? d_G : d_H3;
    __half* Cx = (outMode == 1) ? d_H2x : nullptr;
    int relu = (outMode != 0);

    int tid = threadIdx.x;
    int bm = blockIdx.y * 128;
    int bn = blockIdx.x * 128;
    int lane = tid & 31, w = tid >> 5;
    int wm = w & 1, wn = w >> 1;
    const int m_off = wm*64, n_off = wn*32;
    int gid = lane >> 2, tig = lane & 3;

    float acc[4][4][4];
#pragma unroll
    for (int i = 0; i < 4; i++)
#pragma unroll
        for (int j = 0; j < 4; j++)
#pragma unroll
            for (int q = 0; q < 4; q++) acc[i][j][q] = 0.f;

    int nk = K >> 5;

    // prefetch tile 0 into stage 0
#pragma unroll
    for (int rr = 0; rr < 2; rr++) {
        int q = tid + rr*256;
        int row = q >> 2, c8 = (q & 3)*8;
        CP16(smem_u32(&sm[AA_OFF + row*40 + c8]), A  + (size_t)(bm + row)*K + c8);
        CP16(smem_u32(&sm[BH_OFF + row*40 + c8]), Bt + (size_t)(bn + row)*K + c8);
    }
    CP_COMMIT();

    for (int kt = 0; kt < nk; kt++) {
        int cur = kt & 1;
        const __half* st = sm + cur*STG_ELEMS;
        if (kt + 1 < nk) {
            int k0 = (kt + 1) << 5;
            __half* nx = (__half*)sm + (cur ^ 1)*STG_ELEMS;
#pragma unroll
            for (int rr = 0; rr < 2; rr++) {
                int q = tid + rr*256;
                int row = q >> 2, c8 = (q & 3)*8;
                CP16(smem_u32(&nx[AA_OFF + row*40 + c8]), A  + (size_t)(bm + row)*K + k0 + c8);
                CP16(smem_u32(&nx[BH_OFF + row*40 + c8]), Bt + (size_t)(bn + row)*K + k0 + c8);
            }
            CP_COMMIT();
            CP_WAIT1();          // tile kt's group complete; kt+1 in flight
        } else {
            CP_WAIT0();          // tail: drain everything
        }
        __syncthreads();

#pragma unroll
        for (int kk = 0; kk < 2; kk++) {
            int kc = kk*16 + tig*2;
            uint32_t af[4][4];
#pragma unroll
            for (int mi = 0; mi < 4; mi++) {
                const __half* pa = &st[AA_OFF + (m_off + mi*16 + gid)*40 + kc];
                af[mi][0] = *(const uint32_t*)(pa);
                af[mi][1] = *(const uint32_t*)(pa + 8*40);
                af[mi][2] = *(const uint32_t*)(pa + 8);
                af[mi][3] = *(const uint32_t*)(pa + 8*40 + 8);
            }
            uint32_t bh[4][2];
#pragma unroll
            for (int nj = 0; nj < 4; nj++) {
                const __half* pbh = &st[BH_OFF + (n_off + nj*8 + gid)*40 + kc];
                bh[nj][0] = *(const uint32_t*)(pbh);
                bh[nj][1] = *(const uint32_t*)(pbh + 8);
            }
#pragma unroll
            for (int mi = 0; mi < 4; mi++)
#pragma unroll
                for (int nj = 0; nj < 4; nj++)
                    asm volatile(
                        "mma.sync.aligned.m16n8k16.row.col.f32.f16.f16.f32 "
                        "{%0,%1,%2,%3}, {%4,%5,%6,%7}, {%8,%9}, {%0,%1,%2,%3};"
                        : "+f"(acc[mi][nj][0]), "+f"(acc[mi][nj][1]),
                          "+f"(acc[mi][nj][2]), "+f"(acc[mi][nj][3])
                        : "r"(af[mi][0]), "r"(af[mi][1]), "r"(af[mi][2]), "r"(af[mi][3]),
                          "r"(bh[nj][0]), "r"(bh[nj][1]));
        }
        __syncthreads();
    }

    // epilogue
#pragma unroll
    for (int mi = 0; mi < 4; mi++) {
        int r0 = bm + m_off + mi*16 + gid;
#pragma unroll
        for (int nj = 0; nj < 4; nj++) {
            int c = bn + n_off + nj*8 + tig*2;
            float bb0 = bias ? bias[c]   : 0.f;
            float bb1 = bias ? bias[c+1] : 0.f;
#pragma unroll
            for (int half = 0; half < 2; half++) {
                int r = r0 + half*8;
                float v0 = acc[mi][nj][half*2+0] + bb0;
                float v1 = acc[mi][nj][half*2+1] + bb1;
                if (relu) { v0 = fmaxf(v0, 0.f); v1 = fmaxf(v1, 0.f); }
                if (Cx) {
                    uint32_t* po = (uint32_t*)Cx;
                    po[((size_t)r*N + c) >> 1] =
                        pack_h2(__float2half_rn(v0), __float2half_rn(v1));
                } else {
                    float2 v; v.x = v0; v.y = v1;
                    *(float2*)&Cf[(size_t)r*N + c] = v;
                }
            }
        }
    }
}

// ---------------- K5: assemble plain fp16 H1 (reads precomputed float std) ---
__global__ void k_h1(const float* __restrict__ w1, const float* __restrict__ b1,
                     const float* __restrict__ thr) {
    int r = blockIdx.x;
    int b = r / NPAIR;
    int p = r - b*NPAIR;
    int i = d_pi[p], j = d_pj[p];
    float sim = (d_cos[(b*NEN + i)*NEN + j] - thr[0]) / (d_std[b] + 1e-5f);
    const float* g1 = d_G + (size_t)(b*NEN + i)*1536;
    const float* g2 = d_G + (size_t)(b*NEN + j)*1536 + HSZ;
    uint32_t* po = (uint32_t*)(d_H1x + (size_t)r*HSZ);
    int pidx = threadIdx.x;              // 384 threads, one col-pair each
    int c = pidx*2;
    float v0 = fmaxf(g1[c]   + g2[c]   + sim*w1[c]   + b1[c],   0.f);
    float v1 = fmaxf(g1[c+1] + g2[c+1] + sim*w1[c+1] + b1[c+1], 0.f);
    po[pidx] = pack_h2(__float2half_rn(v0), __float2half_rn(v1));
}

// ---------------- K6: final tiny layer ---------------------------------------
__global__ void k_out(const float* __restrict__ w4, const float* __restrict__ b4,
                      float* __restrict__ out) {
    __shared__ float wsh[H3DIM*2];
    int t = threadIdx.x;
    wsh[t]       = w4[t];
    wsh[t + 256] = w4[t + 256];
    __syncthreads();
    int warp = t >> 5, lane = t & 31;
    int r = blockIdx.x*8 + warp;
    const float* h = d_H3 + (size_t)r*H3DIM;
    float s0 = 0.f, s1 = 0.f;
    for (int c = lane; c < H3DIM; c += 32) {
        float hv = h[c];
        s0 = fmaf(hv, wsh[c*2+0], s0);
        s1 = fmaf(hv, wsh[c*2+1], s1);
    }
#pragma unroll
    for (int o = 16; o; o >>= 1) {
        s0 += __shfl_xor_sync(0xffffffffu, s0, o);
        s1 += __shfl_xor_sync(0xffffffffu, s1, o);
    }
    if (lane == 0) {
        out[r*2 + 0] = s0 + b4[0];
        out[r*2 + 1] = s1 + b4[1];
    }
}

// ---------------- launch -----------------------------------------------------
extern "C" void kernel_launch(void* const* d_in, const int* in_sizes, int n_in,
                              void* d_out, int out_size) {
    const float* x      = (const float*)d_in[0];
    const float* thr    = (const float*)d_in[1];
    const float* w1     = (const float*)d_in[2];
    const float* b1     = (const float*)d_in[3];
    const float* w2     = (const float*)d_in[4];
    const float* b2     = (const float*)d_in[5];
    const float* w3     = (const float*)d_in[6];
    const float* b3     = (const float*)d_in[7];
    const float* w4     = (const float*)d_in[8];
    const float* b4     = (const float*)d_in[9];
    const int*   starts = (const int*)d_in[10];
    float* out = (float*)d_out;

    cudaFuncSetAttribute(gemm_fp16, cudaFuncAttributeMaxDynamicSharedMemorySize,
                         SMEM_GEMM);

    // preprocessing (wide grids — parallelism preserved; fp64 isolated in k_std)
    k_emb<<<BSZ*NEN, 256>>>(x, starts);
    k_pairs<<<1, 64>>>();
    dim3 gcos(NEN, BSZ);
    k_cos<<<gcos, 256>>>();
    k_std<<<BSZ, 256>>>();

    // weight transposes (all single-plane fp16)
    k_expand_w1_t<<<(1536*HSZ + 255)/256, 256>>>(w1);
    k_expand_t<<<(HSZ*H2DIM + 255)/256, 256>>>(w2, 1, HSZ, H2DIM);
    k_expand_t<<<(H2DIM*H3DIM + 255)/256, 256>>>(w3, 2, H2DIM, H3DIM);

    // G = emb @ [w1a|w1b]   (1024 x 1536, K=768) -> d_G fp32
    {
        dim3 g(1536/128, (BSZ*NEN)/128);     // (12, 8)
        gemm_fp16<<<g, 256, SMEM_GEMM>>>(0, 0, nullptr, 0, BSZ*NEN, 1536, HSZ);
    }

    // H1 assembly -> plain fp16
    k_h1<<<NROWS, 384>>>(w1, b1, thr);

    // layer 2: H2x = relu(H1 @ w2 + b2) fp16   (32256 x 512, K=768)
    {
        dim3 g(H2DIM/128, NROWS/128);        // (4, 252)
        gemm_fp16<<<g, 256, SMEM_GEMM>>>(1, 1, b2, 1, NROWS, H2DIM, HSZ);
    }
    // layer 3: H3 = relu(H2 @ w3 + b3) fp32   (32256 x 256, K=512)
    {
        dim3 g(H3DIM/128, NROWS/128);        // (2, 252)
        gemm_fp16<<<g, 256, SMEM_GEMM>>>(2, 2, b3, 2, NROWS, H3DIM, H2DIM);
    }
    // layer 4
    k_out<<<NROWS/8, 256>>>(w4, b4, out);
}